// round 7
// baseline (speedup 1.0000x reference)
#include <cuda_runtime.h>
#include <cuda_fp16.h>
#include <math.h>
#include <stdint.h>

// ---------------------------------------------------------------------------
// Problem constants
#define BB 4
#define SS_ 4096
#define DD 2048
#define HH 1024
#define H2 512
#define EE 8
#define CC 32
#define MM (BB * SS_)   // 16384
#define TAU_F 0.7f

// ---------------------------------------------------------------------------
// Scratch (device globals; no allocations allowed)
__device__ __half g_xhi[(size_t)MM * DD];
__device__ __half g_xlo[(size_t)MM * DD];
__device__ __half g_w1hi[(size_t)HH * DD];   // transposed [N=1024, K=2048]
__device__ __half g_w1lo[(size_t)HH * DD];
__device__ __half g_h1hi[(size_t)MM * HH];
__device__ __half g_h1lo[(size_t)MM * HH];
__device__ __half g_w2hi[(size_t)H2 * HH];   // transposed [N=512, K=1024]
__device__ __half g_w2lo[(size_t)H2 * HH];
__device__ float  g_h2[(size_t)MM * H2];
__device__ float  g_cl[BB * CC * EE];
__device__ int    g_sidx[BB * CC];

// ---------------------------------------------------------------------------
__device__ __forceinline__ uint32_t smem_u32(const void* p) {
    uint32_t a;
    asm("{ .reg .u64 t; cvta.to.shared.u64 t, %1; cvt.u32.u64 %0, t; }"
        : "=r"(a) : "l"(p));
    return a;
}
__device__ __forceinline__ void cp16(uint32_t saddr, const void* gaddr) {
    asm volatile("cp.async.cg.shared.global [%0], [%1], 16;" :: "r"(saddr), "l"(gaddr));
}
#define CP_COMMIT() asm volatile("cp.async.commit_group;" ::: "memory")
#define CP_WAIT(n)  asm volatile("cp.async.wait_group %0;" :: "n"(n) : "memory")

__device__ __forceinline__ void ldsm4(uint32_t* r, uint32_t addr) {
    asm volatile("ldmatrix.sync.aligned.m8n8.x4.shared.b16 {%0,%1,%2,%3}, [%4];"
        : "=r"(r[0]), "=r"(r[1]), "=r"(r[2]), "=r"(r[3]) : "r"(addr));
}
__device__ __forceinline__ void mma16816(float* d, const uint32_t* a, const uint32_t* b) {
    asm volatile("mma.sync.aligned.m16n8k16.row.col.f32.f16.f16.f32 "
        "{%0,%1,%2,%3}, {%4,%5,%6,%7}, {%8,%9}, {%0,%1,%2,%3};"
        : "+f"(d[0]), "+f"(d[1]), "+f"(d[2]), "+f"(d[3])
        : "r"(a[0]), "r"(a[1]), "r"(a[2]), "r"(a[3]), "r"(b[0]), "r"(b[1]));
}

// ---------------------------------------------------------------------------
// Split-precision conversion: fp32 -> (hi, lo) fp16, same layout
__global__ void convert_split(const float* __restrict__ in, __half* __restrict__ ohi,
                              __half* __restrict__ olo, size_t n4)
{
    size_t i = (size_t)blockIdx.x * blockDim.x + threadIdx.x;
    size_t stride = (size_t)gridDim.x * blockDim.x;
    for (; i < n4; i += stride) {
        float4 v = reinterpret_cast<const float4*>(in)[i];
        __half h0 = __float2half_rn(v.x), h1 = __float2half_rn(v.y);
        __half h2 = __float2half_rn(v.z), h3 = __float2half_rn(v.w);
        __half l0 = __float2half_rn(v.x - __half2float(h0));
        __half l1 = __float2half_rn(v.y - __half2float(h1));
        __half l2 = __float2half_rn(v.z - __half2float(h2));
        __half l3 = __float2half_rn(v.w - __half2float(h3));
        reinterpret_cast<__half2*>(ohi)[i * 2]     = __halves2half2(h0, h1);
        reinterpret_cast<__half2*>(ohi)[i * 2 + 1] = __halves2half2(h2, h3);
        reinterpret_cast<__half2*>(olo)[i * 2]     = __halves2half2(l0, l1);
        reinterpret_cast<__half2*>(olo)[i * 2 + 1] = __halves2half2(l2, l3);
    }
}

// Transposing split: in [K, N] fp32 row-major -> out hi/lo [N, K] fp16
__global__ void transpose_split(const float* __restrict__ in, int K, int N,
                                __half* __restrict__ ohi, __half* __restrict__ olo)
{
    __shared__ float t[32][33];
    int nb = blockIdx.x * 32, kb = blockIdx.y * 32;
    int tx = threadIdx.x, ty = threadIdx.y;  // (32, 8)
#pragma unroll
    for (int i = 0; i < 4; i++) {
        int kr = kb + ty + i * 8;
        t[ty + i * 8][tx] = in[(size_t)kr * N + nb + tx];
    }
    __syncthreads();
#pragma unroll
    for (int i = 0; i < 4; i++) {
        int nr = nb + ty + i * 8;
        float v = t[tx][ty + i * 8];
        __half h = __float2half_rn(v);
        __half l = __float2half_rn(v - __half2float(h));
        ohi[(size_t)nr * K + kb + tx] = h;
        olo[(size_t)nr * K + kb + tx] = l;
    }
}

// ---------------------------------------------------------------------------
// Split-fp16 HMMA GEMM:  C[128, 128] = relu(A·B^T + bias)
// A: [M, K] hi/lo fp16 K-major;  B: [N, K] hi/lo fp16 K-major.
// 512 threads = 16 warps (4 x 4), warp tile 32x32, mma.sync m16n8k16.
// 3-stage cp.async pipeline, one barrier per iteration.
// mode 0: write hi/lo fp16 (h1).  mode 1: write fp32 (h2).
// ---------------------------------------------------------------------------
#define BM 128
#define BN 128
#define BKH 32          // K halves per stage
#define PITCH 40        // halves per smem row (80 B, conflict-friendly)
#define ARR_BYTES (BM * PITCH * 2)      // 10240 per array
#define SB_STAGE  (4 * ARR_BYTES)       // 40960: Ahi, Alo, Bhi, Blo
#define NSTAGE 3
#define GEMM_SMEM (NSTAGE * SB_STAGE)   // 122880

__global__ __launch_bounds__(512, 1) void gemm_hmma_x3(
    const __half* __restrict__ Ahi, const __half* __restrict__ Alo,
    const __half* __restrict__ Bhi, const __half* __restrict__ Blo,
    const float* __restrict__ bias, int K, int ldc, int mode,
    __half* __restrict__ Ohi, __half* __restrict__ Olo, float* __restrict__ Of)
{
    extern __shared__ char smem[];
    const uint32_t sb = smem_u32(smem);
    const int tid = threadIdx.x, wid = tid >> 5, lane = tid & 31;
    const int m0 = blockIdx.y * BM, n0 = blockIdx.x * BN;
    const int wm = wid & 3, wn = wid >> 2;     // warp grid 4 x 4, tile 32x32
    const int NC = K / BKH;

    float acc[2][4][4];
#pragma unroll
    for (int i = 0; i < 2; i++)
#pragma unroll
        for (int j = 0; j < 4; j++)
#pragma unroll
            for (int k = 0; k < 4; k++) acc[i][j][k] = 0.0f;

    // stage loader: 4 arrays x 512 16B segments, 1 per thread per array
    auto load_stage = [&](int s, int kc) {
        uint32_t st = sb + s * SB_STAGE;
        const int row = tid >> 2, seg = tid & 3;     // 128 rows x 4 x 16B
        const uint32_t so = row * (PITCH * 2) + seg * 16;
        const size_t ga = (size_t)(m0 + row) * K + kc + seg * 8;
        const size_t gb = (size_t)(n0 + row) * K + kc + seg * 8;
        cp16(st + so,                 Ahi + ga);
        cp16(st + ARR_BYTES + so,     Alo + ga);
        cp16(st + 2 * ARR_BYTES + so, Bhi + gb);
        cp16(st + 3 * ARR_BYTES + so, Blo + gb);
        CP_COMMIT();
    };

    // per-lane ldmatrix addresses
    const int grp = lane >> 3, lr = lane & 7;
    const int a_row = (grp & 1) * 8 + lr;          // + m-tile base
    const int a_k   = (grp >> 1) * 8;
    const int b_row = (grp >> 1) * 8 + lr;         // + n-pair base
    const int b_k   = (grp & 1) * 8;

    // fragment buffers (single-buffered; 4 warps/SMSP hide ldsm latency)
    uint32_t ah[2][4], al[2][4], bh[2][4], bl[2][4];

    auto load_frags = [&](int k16, uint32_t st) {
        const int koff = k16 * 16;
#pragma unroll
        for (int mt = 0; mt < 2; mt++) {
            uint32_t ao = (uint32_t)((wm * 32 + mt * 16 + a_row) * (PITCH * 2)
                                     + (koff + a_k) * 2);
            ldsm4(ah[mt], st + ao);
            ldsm4(al[mt], st + ARR_BYTES + ao);
        }
#pragma unroll
        for (int np = 0; np < 2; np++) {
            uint32_t bo = (uint32_t)((wn * 32 + np * 16 + b_row) * (PITCH * 2)
                                     + (koff + b_k) * 2);
            ldsm4(bh[np], st + 2 * ARR_BYTES + bo);
            ldsm4(bl[np], st + 3 * ARR_BYTES + bo);
        }
    };

    // prologue: 2 stages in flight
    load_stage(0, 0);
    load_stage(1, BKH);

    for (int c = 0; c < NC; c++) {
        // stage c arrived for THIS warp; barrier makes it true for all warps
        // and proves stage c-1 is consumed, so its slot can be reloaded.
        if (c == NC - 1) { CP_WAIT(0); } else { CP_WAIT(1); }
        __syncthreads();
        if (c + 2 < NC) load_stage((c + 2) % NSTAGE, (c + 2) * BKH);

        const uint32_t st = sb + (c % NSTAGE) * SB_STAGE;
#pragma unroll
        for (int k16 = 0; k16 < 2; k16++) {
            load_frags(k16, st);
            // pass hh
#pragma unroll
            for (int mt = 0; mt < 2; mt++)
#pragma unroll
                for (int nt = 0; nt < 4; nt++)
                    mma16816(acc[mt][nt], ah[mt], &bh[nt >> 1][(nt & 1) * 2]);
            // pass hl
#pragma unroll
            for (int mt = 0; mt < 2; mt++)
#pragma unroll
                for (int nt = 0; nt < 4; nt++)
                    mma16816(acc[mt][nt], ah[mt], &bl[nt >> 1][(nt & 1) * 2]);
            // pass lh
#pragma unroll
            for (int mt = 0; mt < 2; mt++)
#pragma unroll
                for (int nt = 0; nt < 4; nt++)
                    mma16816(acc[mt][nt], al[mt], &bh[nt >> 1][(nt & 1) * 2]);
        }
    }

    // epilogue: bias + relu + store
    const int cr = lane >> 2, ccol = (lane & 3) * 2;
#pragma unroll
    for (int mt = 0; mt < 2; mt++) {
#pragma unroll
        for (int nt = 0; nt < 4; nt++) {
            float* a4 = acc[mt][nt];
            int r0 = m0 + wm * 32 + mt * 16 + cr;
            int col = n0 + wn * 32 + nt * 8 + ccol;
            float bz0 = bias[col], bz1 = bias[col + 1];
            float v00 = fmaxf(a4[0] + bz0, 0.0f);
            float v01 = fmaxf(a4[1] + bz1, 0.0f);
            float v10 = fmaxf(a4[2] + bz0, 0.0f);
            float v11 = fmaxf(a4[3] + bz1, 0.0f);
            if (mode == 0) {
                __half h00 = __float2half_rn(v00), h01 = __float2half_rn(v01);
                __half h10 = __float2half_rn(v10), h11 = __float2half_rn(v11);
                __half l00 = __float2half_rn(v00 - __half2float(h00));
                __half l01 = __float2half_rn(v01 - __half2float(h01));
                __half l10 = __float2half_rn(v10 - __half2float(h10));
                __half l11 = __float2half_rn(v11 - __half2float(h11));
                *reinterpret_cast<__half2*>(Ohi + (size_t)r0 * ldc + col) = __halves2half2(h00, h01);
                *reinterpret_cast<__half2*>(Ohi + (size_t)(r0 + 8) * ldc + col) = __halves2half2(h10, h11);
                *reinterpret_cast<__half2*>(Olo + (size_t)r0 * ldc + col) = __halves2half2(l00, l01);
                *reinterpret_cast<__half2*>(Olo + (size_t)(r0 + 8) * ldc + col) = __halves2half2(l10, l11);
            } else {
                float2 f0 = {v00, v01}, f1 = {v10, v11};
                *reinterpret_cast<float2*>(Of + (size_t)r0 * ldc + col) = f0;
                *reinterpret_cast<float2*>(Of + (size_t)(r0 + 8) * ldc + col) = f1;
            }
        }
    }
}

// ---------------------------------------------------------------------------
// GEMM3 fused with per-chunk mean (reads g_h2)
__global__ void chunk_logits_kernel(const float* __restrict__ w3,
                                    const float* __restrict__ b3)
{
    __shared__ float w3s[H2 * EE];
    __shared__ float red[4][EE];
    const int tid = threadIdx.x;  // 128

    for (int i = tid; i < H2 * EE; i += 128) w3s[i] = w3[i];
    __syncthreads();

    const size_t tok = (size_t)blockIdx.x * 128 + tid;
    const float* hrow = g_h2 + tok * H2;
    float acc[EE];
#pragma unroll
    for (int e = 0; e < EE; e++) acc[e] = 0.0f;
    for (int k = 0; k < H2; k += 4) {
        float4 hv = *reinterpret_cast<const float4*>(hrow + k);
#pragma unroll
        for (int e = 0; e < EE; e++) {
            acc[e] = fmaf(hv.x, w3s[(k + 0) * EE + e], acc[e]);
            acc[e] = fmaf(hv.y, w3s[(k + 1) * EE + e], acc[e]);
            acc[e] = fmaf(hv.z, w3s[(k + 2) * EE + e], acc[e]);
            acc[e] = fmaf(hv.w, w3s[(k + 3) * EE + e], acc[e]);
        }
    }
    const int lane = tid & 31, warp = tid >> 5;
#pragma unroll
    for (int e = 0; e < EE; e++) {
        float v = acc[e];
#pragma unroll
        for (int o = 16; o > 0; o >>= 1) v += __shfl_down_sync(0xffffffffu, v, o);
        if (lane == 0) red[warp][e] = v;
    }
    __syncthreads();
    if (tid < EE) {
        float s = red[0][tid] + red[1][tid] + red[2][tid] + red[3][tid];
        g_cl[blockIdx.x * EE + tid] = s * (1.0f / 128.0f) + b3[tid];
    }
}

// ---------------------------------------------------------------------------
// finalize (1 block): hysteresis + stats + small outputs; saves sidx
__global__ void finalize_kernel(float* __restrict__ out)
{
    __shared__ float scl[BB * CC * EE];
    __shared__ int   sidx[BB * CC];
    __shared__ int   sflips[BB];
    __shared__ float sent[BB * CC];
    __shared__ float sutil[EE];
    __shared__ float sscal[3];
    const int tid = threadIdx.x;  // 128

    for (int i = tid; i < BB * CC * EE; i += 128) scl[i] = g_cl[i];
    if (tid < EE) sutil[tid] = 0.0f;
    __syncthreads();

    if (tid < BB) {
        int b = tid, prev = 0, flips = 0;
        for (int c = 0; c < CC; c++) {
            const float* l = &scl[(b * CC + c) * EE];
            int top = 0; float best = l[0];
#pragma unroll
            for (int e = 1; e < EE; e++)
                if (l[e] > best) { best = l[e]; top = e; }
            int fin;
            if (c == 0) fin = top;
            else {
                bool sw = (l[top] - l[prev]) > TAU_F;
                flips += sw ? 1 : 0;
                fin = sw ? top : prev;
            }
            sidx[b * CC + c] = fin;
            prev = fin;
        }
        sflips[tid] = flips;
    }
    __syncthreads();

    {
        const float* l = &scl[tid * EE];
        float mx = l[0];
#pragma unroll
        for (int e = 1; e < EE; e++) mx = fmaxf(mx, l[e]);
        float p[EE], se = 0.0f;
#pragma unroll
        for (int e = 0; e < EE; e++) { p[e] = expf(l[e] - mx); se += p[e]; }
        float ent = 0.0f, inv = 1.0f / se;
#pragma unroll
        for (int e = 0; e < EE; e++) {
            float pr = p[e] * inv;
            ent -= pr * logf(pr + 1e-8f);
        }
        sent[tid] = ent;
        atomicAdd(&sutil[sidx[tid]], 1.0f);
    }
    __syncthreads();

    if (tid == 0) {
        float es = 0.0f;
        for (int i = 0; i < BB * CC; i++) es += sent[i];
        sscal[0] = es / (float)(BB * CC);
        int fl = sflips[0] + sflips[1] + sflips[2] + sflips[3];
        sscal[1] = (float)fl / (float)(BB * (CC - 1));
        float nrm = 0.0f;
        for (int e = 0; e < EE; e++) {
            float u = sutil[e] / (float)(BB * CC);
            nrm += u * u;
        }
        sscal[2] = sqrtf(nrm);
    }
    __syncthreads();

    if (tid < BB * CC) { g_sidx[tid] = sidx[tid]; out[131072 + tid] = (float)sidx[tid]; }
    for (int i = tid; i < BB * CC * EE; i += 128) out[131200 + i] = scl[i];
    if (tid == 0) out[132224] = sscal[0];
    if (tid < EE) out[132225 + tid] = sutil[tid] / (float)(BB * CC);
    if (tid == 0) { out[132233] = sscal[1]; out[132234] = sscal[2]; }
}

// Wide routing_weights writer: one token (8 floats) per thread
__global__ void routing_weights_kernel(float* __restrict__ out)
{
    int t = blockIdx.x * blockDim.x + threadIdx.x;   // 0..16383
    int b = t >> 12;
    int c = (t >> 7) & 31;
    int id = g_sidx[b * CC + c];
    float vv[EE];
#pragma unroll
    for (int e = 0; e < EE; e++) vv[e] = (e == id) ? 1.0f : 0.0f;
    float4 v0 = {vv[0], vv[1], vv[2], vv[3]};
    float4 v1 = {vv[4], vv[5], vv[6], vv[7]};
    *reinterpret_cast<float4*>(out + (size_t)t * EE)     = v0;
    *reinterpret_cast<float4*>(out + (size_t)t * EE + 4) = v1;
}

// ---------------------------------------------------------------------------
extern "C" void kernel_launch(void* const* d_in, const int* in_sizes, int n_in,
                              void* d_out, int out_size)
{
    const float* x  = (const float*)d_in[0];
    // d_in[1] = prev_expert_indices — dead in reference (chunk 0 takes argmax)
    const float* w1 = (const float*)d_in[2];
    const float* b1 = (const float*)d_in[3];
    const float* w2 = (const float*)d_in[4];
    const float* b2 = (const float*)d_in[5];
    const float* w3 = (const float*)d_in[6];
    const float* b3 = (const float*)d_in[7];
    float* out = (float*)d_out;

    cudaFuncSetAttribute(gemm_hmma_x3, cudaFuncAttributeMaxDynamicSharedMemorySize, GEMM_SMEM);

    __half *xhi, *xlo, *w1hi, *w1lo, *h1hi, *h1lo, *w2hi, *w2lo;
    float *h2;
    cudaGetSymbolAddress((void**)&xhi, g_xhi);
    cudaGetSymbolAddress((void**)&xlo, g_xlo);
    cudaGetSymbolAddress((void**)&w1hi, g_w1hi);
    cudaGetSymbolAddress((void**)&w1lo, g_w1lo);
    cudaGetSymbolAddress((void**)&h1hi, g_h1hi);
    cudaGetSymbolAddress((void**)&h1lo, g_h1lo);
    cudaGetSymbolAddress((void**)&w2hi, g_w2hi);
    cudaGetSymbolAddress((void**)&w2lo, g_w2lo);
    cudaGetSymbolAddress((void**)&h2, g_h2);

    // input conversions
    convert_split<<<2048, 256>>>(x, xhi, xlo, (size_t)MM * DD / 4);
    transpose_split<<<dim3(HH / 32, DD / 32), dim3(32, 8)>>>(w1, DD, HH, w1hi, w1lo);
    transpose_split<<<dim3(H2 / 32, HH / 32), dim3(32, 8)>>>(w2, HH, H2, w2hi, w2lo);

    // GEMM1: [16384,2048] x [2048->1024] -> h1 (hi/lo fp16)
    gemm_hmma_x3<<<dim3(HH / BN, MM / BM), 512, GEMM_SMEM>>>(
        xhi, xlo, w1hi, w1lo, b1, DD, HH, 0, h1hi, h1lo, nullptr);
    // GEMM2: [16384,1024] x [1024->512] -> h2 (fp32)
    gemm_hmma_x3<<<dim3(H2 / BN, MM / BM), 512, GEMM_SMEM>>>(
        h1hi, h1lo, w2hi, w2lo, b2, HH, H2, 1, nullptr, nullptr, h2);

    chunk_logits_kernel<<<BB * CC, 128>>>(w3, b3);
    finalize_kernel<<<1, 128>>>(out);
    routing_weights_kernel<<<MM / 256, 256>>>(out);
}

// round 8
// speedup vs baseline: 1.0227x; 1.0227x over previous
#include <cuda_runtime.h>
#include <cuda_fp16.h>
#include <math.h>
#include <stdint.h>

// ---------------------------------------------------------------------------
// Problem constants
#define BB 4
#define SS_ 4096
#define DD 2048
#define HH 1024
#define H2 512
#define EE 8
#define CC 32
#define MM (BB * SS_)   // 16384
#define TAU_F 0.7f

// ---------------------------------------------------------------------------
// Scratch (device globals; no allocations allowed)
__device__ __half g_xhi[(size_t)MM * DD];
__device__ __half g_xlo[(size_t)MM * DD];
__device__ __half g_w1hi[(size_t)HH * DD];   // transposed [N=1024, K=2048]
__device__ __half g_w1lo[(size_t)HH * DD];
__device__ __half g_h1hi[(size_t)MM * HH];
__device__ __half g_h1lo[(size_t)MM * HH];
__device__ __half g_w2hi[(size_t)H2 * HH];   // transposed [N=512, K=1024]
__device__ __half g_w2lo[(size_t)H2 * HH];
__device__ float  g_h2[(size_t)MM * H2];
__device__ float  g_cl[BB * CC * EE];
__device__ int    g_sidx[BB * CC];

// ---------------------------------------------------------------------------
__device__ __forceinline__ uint32_t smem_u32(const void* p) {
    uint32_t a;
    asm("{ .reg .u64 t; cvta.to.shared.u64 t, %1; cvt.u32.u64 %0, t; }"
        : "=r"(a) : "l"(p));
    return a;
}
__device__ __forceinline__ void cp16(uint32_t saddr, const void* gaddr) {
    asm volatile("cp.async.cg.shared.global [%0], [%1], 16;" :: "r"(saddr), "l"(gaddr));
}
#define CP_COMMIT() asm volatile("cp.async.commit_group;" ::: "memory")
#define CP_WAIT(n)  asm volatile("cp.async.wait_group %0;" :: "n"(n) : "memory")

__device__ __forceinline__ void ldsm4(uint32_t* r, uint32_t addr) {
    asm volatile("ldmatrix.sync.aligned.m8n8.x4.shared.b16 {%0,%1,%2,%3}, [%4];"
        : "=r"(r[0]), "=r"(r[1]), "=r"(r[2]), "=r"(r[3]) : "r"(addr));
}
// fp32-accumulator HMMA (main hi*hi pass)
__device__ __forceinline__ void mma16816(float* d, const uint32_t* a, const uint32_t* b) {
    asm volatile("mma.sync.aligned.m16n8k16.row.col.f32.f16.f16.f32 "
        "{%0,%1,%2,%3}, {%4,%5,%6,%7}, {%8,%9}, {%0,%1,%2,%3};"
        : "+f"(d[0]), "+f"(d[1]), "+f"(d[2]), "+f"(d[3])
        : "r"(a[0]), "r"(a[1]), "r"(a[2]), "r"(a[3]), "r"(b[0]), "r"(b[1]));
}
// fp16-accumulator HMMA (correction passes; terms ~2^-11 of main)
__device__ __forceinline__ void mma16816h(uint32_t* d, const uint32_t* a, const uint32_t* b) {
    asm volatile("mma.sync.aligned.m16n8k16.row.col.f16.f16.f16.f16 "
        "{%0,%1}, {%2,%3,%4,%5}, {%6,%7}, {%0,%1};"
        : "+r"(d[0]), "+r"(d[1])
        : "r"(a[0]), "r"(a[1]), "r"(a[2]), "r"(a[3]), "r"(b[0]), "r"(b[1]));
}

// ---------------------------------------------------------------------------
// Split-precision conversion: fp32 -> (hi, lo) fp16, same layout
__global__ void convert_split(const float* __restrict__ in, __half* __restrict__ ohi,
                              __half* __restrict__ olo, size_t n4)
{
    size_t i = (size_t)blockIdx.x * blockDim.x + threadIdx.x;
    size_t stride = (size_t)gridDim.x * blockDim.x;
    for (; i < n4; i += stride) {
        float4 v = reinterpret_cast<const float4*>(in)[i];
        __half h0 = __float2half_rn(v.x), h1 = __float2half_rn(v.y);
        __half h2 = __float2half_rn(v.z), h3 = __float2half_rn(v.w);
        __half l0 = __float2half_rn(v.x - __half2float(h0));
        __half l1 = __float2half_rn(v.y - __half2float(h1));
        __half l2 = __float2half_rn(v.z - __half2float(h2));
        __half l3 = __float2half_rn(v.w - __half2float(h3));
        reinterpret_cast<__half2*>(ohi)[i * 2]     = __halves2half2(h0, h1);
        reinterpret_cast<__half2*>(ohi)[i * 2 + 1] = __halves2half2(h2, h3);
        reinterpret_cast<__half2*>(olo)[i * 2]     = __halves2half2(l0, l1);
        reinterpret_cast<__half2*>(olo)[i * 2 + 1] = __halves2half2(l2, l3);
    }
}

// Transposing split: in [K, N] fp32 row-major -> out hi/lo [N, K] fp16
__global__ void transpose_split(const float* __restrict__ in, int K, int N,
                                __half* __restrict__ ohi, __half* __restrict__ olo)
{
    __shared__ float t[32][33];
    int nb = blockIdx.x * 32, kb = blockIdx.y * 32;
    int tx = threadIdx.x, ty = threadIdx.y;  // (32, 8)
#pragma unroll
    for (int i = 0; i < 4; i++) {
        int kr = kb + ty + i * 8;
        t[ty + i * 8][tx] = in[(size_t)kr * N + nb + tx];
    }
    __syncthreads();
#pragma unroll
    for (int i = 0; i < 4; i++) {
        int nr = nb + ty + i * 8;
        float v = t[tx][ty + i * 8];
        __half h = __float2half_rn(v);
        __half l = __float2half_rn(v - __half2float(h));
        ohi[(size_t)nr * K + kb + tx] = h;
        olo[(size_t)nr * K + kb + tx] = l;
    }
}

// ---------------------------------------------------------------------------
// Split-fp16 HMMA GEMM:  C[128, 128] = relu(A·B^T + bias)
// hh pass -> fp32 accumulators; hl + lh correction passes -> fp16 accumulators
// (full-rate on sm_103a legacy HMMA pipe; corrections are 2^-11-scale).
// 256 threads = 8 warps (2 x 4), warp tile 64x32, 3-stage cp.async pipeline.
// mode 0: write hi/lo fp16 (h1).  mode 1: write fp32 (h2).
// ---------------------------------------------------------------------------
#define BM 128
#define BN 128
#define BKH 32          // K halves per stage
#define PITCH 40        // halves per smem row (80 B, conflict-friendly)
#define ARR_BYTES (BM * PITCH * 2)      // 10240 per array
#define SB_STAGE  (4 * ARR_BYTES)       // 40960: Ahi, Alo, Bhi, Blo
#define NSTAGE 3
#define GEMM_SMEM (NSTAGE * SB_STAGE)   // 122880

__global__ __launch_bounds__(256, 1) void gemm_hmma_x3(
    const __half* __restrict__ Ahi, const __half* __restrict__ Alo,
    const __half* __restrict__ Bhi, const __half* __restrict__ Blo,
    const float* __restrict__ bias, int K, int ldc, int mode,
    __half* __restrict__ Ohi, __half* __restrict__ Olo, float* __restrict__ Of)
{
    extern __shared__ char smem[];
    const uint32_t sb = smem_u32(smem);
    const int tid = threadIdx.x, wid = tid >> 5, lane = tid & 31;
    const int m0 = blockIdx.y * BM, n0 = blockIdx.x * BN;
    const int wm = wid & 1, wn = wid >> 1;     // warp grid 2 x 4
    const int NC = K / BKH;

    float acc[4][4][4];                // hh pass, fp32
    uint32_t cacc[4][4][2];            // hl+lh corrections, f16x2
#pragma unroll
    for (int i = 0; i < 4; i++)
#pragma unroll
        for (int j = 0; j < 4; j++) {
#pragma unroll
            for (int k = 0; k < 4; k++) acc[i][j][k] = 0.0f;
            cacc[i][j][0] = 0u; cacc[i][j][1] = 0u;
        }

    // stage loader: 4 arrays x 512 16B segments, 2 per thread per array
    auto load_stage = [&](int s, int kc) {
        uint32_t st = sb + s * SB_STAGE;
#pragma unroll
        for (int arr = 0; arr < 4; arr++) {
            const __half* g = (arr == 0) ? Ahi : (arr == 1) ? Alo : (arr == 2) ? Bhi : Blo;
            int rbase = (arr < 2) ? m0 : n0;
            uint32_t base = st + arr * ARR_BYTES;
#pragma unroll
            for (int i = 0; i < 2; i++) {
                int s4 = tid + i * 256;            // 0..511
                int row = s4 >> 2, seg = s4 & 3;   // 4 x 16B per row (64 B)
                cp16(base + row * (PITCH * 2) + seg * 16,
                     g + (size_t)(rbase + row) * K + kc + seg * 8);
            }
        }
        CP_COMMIT();
    };

    // per-lane ldmatrix addresses
    const int grp = lane >> 3, lr = lane & 7;
    const int a_row = (grp & 1) * 8 + lr;          // + m-tile base
    const int a_k   = (grp >> 1) * 8;
    const int b_row = (grp >> 1) * 8 + lr;         // + n-pair base
    const int b_k   = (grp & 1) * 8;

    // fragment buffers (single-buffered)
    uint32_t ah[4][4], al[4][4], bh[2][4], bl[2][4];

    auto load_frags = [&](int k16, uint32_t st) {
        const int koff = k16 * 16;
#pragma unroll
        for (int mt = 0; mt < 4; mt++) {
            uint32_t ao = (uint32_t)((wm * 64 + mt * 16 + a_row) * (PITCH * 2)
                                     + (koff + a_k) * 2);
            ldsm4(ah[mt], st + ao);
            ldsm4(al[mt], st + ARR_BYTES + ao);
        }
#pragma unroll
        for (int np = 0; np < 2; np++) {
            uint32_t bo = (uint32_t)((wn * 32 + np * 16 + b_row) * (PITCH * 2)
                                     + (koff + b_k) * 2);
            ldsm4(bh[np], st + 2 * ARR_BYTES + bo);
            ldsm4(bl[np], st + 3 * ARR_BYTES + bo);
        }
    };

    // prologue: 2 stages in flight
    load_stage(0, 0);
    load_stage(1, BKH);

    for (int c = 0; c < NC; c++) {
        // stage c arrived for THIS warp; barrier makes it true for all warps
        // and proves stage c-1 is consumed, so its slot can be reloaded.
        if (c == NC - 1) { CP_WAIT(0); } else { CP_WAIT(1); }
        __syncthreads();
        if (c + 2 < NC) load_stage((c + 2) % NSTAGE, (c + 2) * BKH);

        const uint32_t st = sb + (c % NSTAGE) * SB_STAGE;
#pragma unroll
        for (int k16 = 0; k16 < 2; k16++) {
            load_frags(k16, st);
            // pass hh (fp32 accum)
#pragma unroll
            for (int mt = 0; mt < 4; mt++)
#pragma unroll
                for (int nt = 0; nt < 4; nt++)
                    mma16816(acc[mt][nt], ah[mt], &bh[nt >> 1][(nt & 1) * 2]);
            // pass hl (fp16 accum)
#pragma unroll
            for (int mt = 0; mt < 4; mt++)
#pragma unroll
                for (int nt = 0; nt < 4; nt++)
                    mma16816h(cacc[mt][nt], ah[mt], &bl[nt >> 1][(nt & 1) * 2]);
            // pass lh (fp16 accum)
#pragma unroll
            for (int mt = 0; mt < 4; mt++)
#pragma unroll
                for (int nt = 0; nt < 4; nt++)
                    mma16816h(cacc[mt][nt], al[mt], &bh[nt >> 1][(nt & 1) * 2]);
        }
    }

    // epilogue: hh + correction + bias, relu, store
    const int cr = lane >> 2, ccol = (lane & 3) * 2;
#pragma unroll
    for (int mt = 0; mt < 4; mt++) {
#pragma unroll
        for (int nt = 0; nt < 4; nt++) {
            float* a4 = acc[mt][nt];
            __half2 c01 = *reinterpret_cast<__half2*>(&cacc[mt][nt][0]);
            __half2 c23 = *reinterpret_cast<__half2*>(&cacc[mt][nt][1]);
            int r0 = m0 + wm * 64 + mt * 16 + cr;
            int col = n0 + wn * 32 + nt * 8 + ccol;
            float bz0 = bias[col], bz1 = bias[col + 1];
            float v00 = fmaxf(a4[0] + __low2float(c01)  + bz0, 0.0f);
            float v01 = fmaxf(a4[1] + __high2float(c01) + bz1, 0.0f);
            float v10 = fmaxf(a4[2] + __low2float(c23)  + bz0, 0.0f);
            float v11 = fmaxf(a4[3] + __high2float(c23) + bz1, 0.0f);
            if (mode == 0) {
                __half h00 = __float2half_rn(v00), h01 = __float2half_rn(v01);
                __half h10 = __float2half_rn(v10), h11 = __float2half_rn(v11);
                __half l00 = __float2half_rn(v00 - __half2float(h00));
                __half l01 = __float2half_rn(v01 - __half2float(h01));
                __half l10 = __float2half_rn(v10 - __half2float(h10));
                __half l11 = __float2half_rn(v11 - __half2float(h11));
                *reinterpret_cast<__half2*>(Ohi + (size_t)r0 * ldc + col) = __halves2half2(h00, h01);
                *reinterpret_cast<__half2*>(Ohi + (size_t)(r0 + 8) * ldc + col) = __halves2half2(h10, h11);
                *reinterpret_cast<__half2*>(Olo + (size_t)r0 * ldc + col) = __halves2half2(l00, l01);
                *reinterpret_cast<__half2*>(Olo + (size_t)(r0 + 8) * ldc + col) = __halves2half2(l10, l11);
            } else {
                float2 f0 = {v00, v01}, f1 = {v10, v11};
                *reinterpret_cast<float2*>(Of + (size_t)r0 * ldc + col) = f0;
                *reinterpret_cast<float2*>(Of + (size_t)(r0 + 8) * ldc + col) = f1;
            }
        }
    }
}

// ---------------------------------------------------------------------------
// GEMM3 fused with per-chunk mean (reads g_h2)
__global__ void chunk_logits_kernel(const float* __restrict__ w3,
                                    const float* __restrict__ b3)
{
    __shared__ float w3s[H2 * EE];
    __shared__ float red[4][EE];
    const int tid = threadIdx.x;  // 128

    for (int i = tid; i < H2 * EE; i += 128) w3s[i] = w3[i];
    __syncthreads();

    const size_t tok = (size_t)blockIdx.x * 128 + tid;
    const float* hrow = g_h2 + tok * H2;
    float acc[EE];
#pragma unroll
    for (int e = 0; e < EE; e++) acc[e] = 0.0f;
    for (int k = 0; k < H2; k += 4) {
        float4 hv = *reinterpret_cast<const float4*>(hrow + k);
#pragma unroll
        for (int e = 0; e < EE; e++) {
            acc[e] = fmaf(hv.x, w3s[(k + 0) * EE + e], acc[e]);
            acc[e] = fmaf(hv.y, w3s[(k + 1) * EE + e], acc[e]);
            acc[e] = fmaf(hv.z, w3s[(k + 2) * EE + e], acc[e]);
            acc[e] = fmaf(hv.w, w3s[(k + 3) * EE + e], acc[e]);
        }
    }
    const int lane = tid & 31, warp = tid >> 5;
#pragma unroll
    for (int e = 0; e < EE; e++) {
        float v = acc[e];
#pragma unroll
        for (int o = 16; o > 0; o >>= 1) v += __shfl_down_sync(0xffffffffu, v, o);
        if (lane == 0) red[warp][e] = v;
    }
    __syncthreads();
    if (tid < EE) {
        float s = red[0][tid] + red[1][tid] + red[2][tid] + red[3][tid];
        g_cl[blockIdx.x * EE + tid] = s * (1.0f / 128.0f) + b3[tid];
    }
}

// ---------------------------------------------------------------------------
// finalize (1 block): hysteresis + stats + small outputs; saves sidx
__global__ void finalize_kernel(float* __restrict__ out)
{
    __shared__ float scl[BB * CC * EE];
    __shared__ int   sidx[BB * CC];
    __shared__ int   sflips[BB];
    __shared__ float sent[BB * CC];
    __shared__ float sutil[EE];
    __shared__ float sscal[3];
    const int tid = threadIdx.x;  // 128

    for (int i = tid; i < BB * CC * EE; i += 128) scl[i] = g_cl[i];
    if (tid < EE) sutil[tid] = 0.0f;
    __syncthreads();

    if (tid < BB) {
        int b = tid, prev = 0, flips = 0;
        for (int c = 0; c < CC; c++) {
            const float* l = &scl[(b * CC + c) * EE];
            int top = 0; float best = l[0];
#pragma unroll
            for (int e = 1; e < EE; e++)
                if (l[e] > best) { best = l[e]; top = e; }
            int fin;
            if (c == 0) fin = top;
            else {
                bool sw = (l[top] - l[prev]) > TAU_F;
                flips += sw ? 1 : 0;
                fin = sw ? top : prev;
            }
            sidx[b * CC + c] = fin;
            prev = fin;
        }
        sflips[tid] = flips;
    }
    __syncthreads();

    {
        const float* l = &scl[tid * EE];
        float mx = l[0];
#pragma unroll
        for (int e = 1; e < EE; e++) mx = fmaxf(mx, l[e]);
        float p[EE], se = 0.0f;
#pragma unroll
        for (int e = 0; e < EE; e++) { p[e] = expf(l[e] - mx); se += p[e]; }
        float ent = 0.0f, inv = 1.0f / se;
#pragma unroll
        for (int e = 0; e < EE; e++) {
            float pr = p[e] * inv;
            ent -= pr * logf(pr + 1e-8f);
        }
        sent[tid] = ent;
        atomicAdd(&sutil[sidx[tid]], 1.0f);
    }
    __syncthreads();

    if (tid == 0) {
        float es = 0.0f;
        for (int i = 0; i < BB * CC; i++) es += sent[i];
        sscal[0] = es / (float)(BB * CC);
        int fl = sflips[0] + sflips[1] + sflips[2] + sflips[3];
        sscal[1] = (float)fl / (float)(BB * (CC - 1));
        float nrm = 0.0f;
        for (int e = 0; e < EE; e++) {
            float u = sutil[e] / (float)(BB * CC);
            nrm += u * u;
        }
        sscal[2] = sqrtf(nrm);
    }
    __syncthreads();

    if (tid < BB * CC) { g_sidx[tid] = sidx[tid]; out[131072 + tid] = (float)sidx[tid]; }
    for (int i = tid; i < BB * CC * EE; i += 128) out[131200 + i] = scl[i];
    if (tid == 0) out[132224] = sscal[0];
    if (tid < EE) out[132225 + tid] = sutil[tid] / (float)(BB * CC);
    if (tid == 0) { out[132233] = sscal[1]; out[132234] = sscal[2]; }
}

// Wide routing_weights writer: one token (8 floats) per thread
__global__ void routing_weights_kernel(float* __restrict__ out)
{
    int t = blockIdx.x * blockDim.x + threadIdx.x;   // 0..16383
    int b = t >> 12;
    int c = (t >> 7) & 31;
    int id = g_sidx[b * CC + c];
    float vv[EE];
#pragma unroll
    for (int e = 0; e < EE; e++) vv[e] = (e == id) ? 1.0f : 0.0f;
    float4 v0 = {vv[0], vv[1], vv[2], vv[3]};
    float4 v1 = {vv[4], vv[5], vv[6], vv[7]};
    *reinterpret_cast<float4*>(out + (size_t)t * EE)     = v0;
    *reinterpret_cast<float4*>(out + (size_t)t * EE + 4) = v1;
}

// ---------------------------------------------------------------------------
extern "C" void kernel_launch(void* const* d_in, const int* in_sizes, int n_in,
                              void* d_out, int out_size)
{
    const float* x  = (const float*)d_in[0];
    // d_in[1] = prev_expert_indices — dead in reference (chunk 0 takes argmax)
    const float* w1 = (const float*)d_in[2];
    const float* b1 = (const float*)d_in[3];
    const float* w2 = (const float*)d_in[4];
    const float* b2 = (const float*)d_in[5];
    const float* w3 = (const float*)d_in[6];
    const float* b3 = (const float*)d_in[7];
    float* out = (float*)d_out;

    cudaFuncSetAttribute(gemm_hmma_x3, cudaFuncAttributeMaxDynamicSharedMemorySize, GEMM_SMEM);

    __half *xhi, *xlo, *w1hi, *w1lo, *h1hi, *h1lo, *w2hi, *w2lo;
    float *h2;
    cudaGetSymbolAddress((void**)&xhi, g_xhi);
    cudaGetSymbolAddress((void**)&xlo, g_xlo);
    cudaGetSymbolAddress((void**)&w1hi, g_w1hi);
    cudaGetSymbolAddress((void**)&w1lo, g_w1lo);
    cudaGetSymbolAddress((void**)&h1hi, g_h1hi);
    cudaGetSymbolAddress((void**)&h1lo, g_h1lo);
    cudaGetSymbolAddress((void**)&w2hi, g_w2hi);
    cudaGetSymbolAddress((void**)&w2lo, g_w2lo);
    cudaGetSymbolAddress((void**)&h2, g_h2);

    // input conversions
    convert_split<<<2048, 256>>>(x, xhi, xlo, (size_t)MM * DD / 4);
    transpose_split<<<dim3(HH / 32, DD / 32), dim3(32, 8)>>>(w1, DD, HH, w1hi, w1lo);
    transpose_split<<<dim3(H2 / 32, HH / 32), dim3(32, 8)>>>(w2, HH, H2, w2hi, w2lo);

    // GEMM1: [16384,2048] x [2048->1024] -> h1 (hi/lo fp16)
    gemm_hmma_x3<<<dim3(HH / BN, MM / BM), 256, GEMM_SMEM>>>(
        xhi, xlo, w1hi, w1lo, b1, DD, HH, 0, h1hi, h1lo, nullptr);
    // GEMM2: [16384,1024] x [1024->512] -> h2 (fp32)
    gemm_hmma_x3<<<dim3(H2 / BN, MM / BM), 256, GEMM_SMEM>>>(
        h1hi, h1lo, w2hi, w2lo, b2, HH, H2, 1, nullptr, nullptr, h2);

    chunk_logits_kernel<<<BB * CC, 128>>>(w3, b3);
    finalize_kernel<<<1, 128>>>(out);
    routing_weights_kernel<<<MM / 256, 256>>>(out);
}

// round 9
// speedup vs baseline: 1.0656x; 1.0419x over previous
#include <cuda_runtime.h>
#include <cuda_fp16.h>
#include <math.h>
#include <stdint.h>

// ---------------------------------------------------------------------------
// Problem constants
#define BB 4
#define SS_ 4096
#define DD 2048
#define HH 1024
#define H2 512
#define EE 8
#define CC 32
#define MM (BB * SS_)   // 16384
#define TAU_F 0.7f

// ---------------------------------------------------------------------------
// Scratch (device globals; no allocations allowed)
__device__ __half g_xhi[(size_t)MM * DD];
__device__ __half g_xlo[(size_t)MM * DD];
__device__ __half g_w1hi[(size_t)HH * DD];   // transposed [N=1024, K=2048]
__device__ __half g_w1lo[(size_t)HH * DD];
__device__ __half g_h1hi[(size_t)MM * HH];
__device__ __half g_h1lo[(size_t)MM * HH];
__device__ __half g_w2hi[(size_t)H2 * HH];   // transposed [N=512, K=1024]
__device__ __half g_w2lo[(size_t)H2 * HH];
__device__ float  g_h2[(size_t)MM * H2];
__device__ float  g_cl[BB * CC * EE];
__device__ int    g_sidx[BB * CC];

// ---------------------------------------------------------------------------
__device__ __forceinline__ uint32_t smem_u32(const void* p) {
    uint32_t a;
    asm("{ .reg .u64 t; cvta.to.shared.u64 t, %1; cvt.u32.u64 %0, t; }"
        : "=r"(a) : "l"(p));
    return a;
}
__device__ __forceinline__ void cp16(uint32_t saddr, const void* gaddr) {
    asm volatile("cp.async.cg.shared.global [%0], [%1], 16;" :: "r"(saddr), "l"(gaddr));
}
#define CP_COMMIT() asm volatile("cp.async.commit_group;" ::: "memory")
#define CP_WAIT(n)  asm volatile("cp.async.wait_group %0;" :: "n"(n) : "memory")

__device__ __forceinline__ void ldsm4(uint32_t* r, uint32_t addr) {
    asm volatile("ldmatrix.sync.aligned.m8n8.x4.shared.b16 {%0,%1,%2,%3}, [%4];"
        : "=r"(r[0]), "=r"(r[1]), "=r"(r[2]), "=r"(r[3]) : "r"(addr));
}
// fp32-accumulator HMMA (main hi*hi pass)
__device__ __forceinline__ void mma16816(float* d, const uint32_t* a, const uint32_t* b) {
    asm volatile("mma.sync.aligned.m16n8k16.row.col.f32.f16.f16.f32 "
        "{%0,%1,%2,%3}, {%4,%5,%6,%7}, {%8,%9}, {%0,%1,%2,%3};"
        : "+f"(d[0]), "+f"(d[1]), "+f"(d[2]), "+f"(d[3])
        : "r"(a[0]), "r"(a[1]), "r"(a[2]), "r"(a[3]), "r"(b[0]), "r"(b[1]));
}
// fp16-accumulator HMMA (correction passes; terms ~2^-11 of main)
__device__ __forceinline__ void mma16816h(uint32_t* d, const uint32_t* a, const uint32_t* b) {
    asm volatile("mma.sync.aligned.m16n8k16.row.col.f16.f16.f16.f16 "
        "{%0,%1}, {%2,%3,%4,%5}, {%6,%7}, {%0,%1};"
        : "+r"(d[0]), "+r"(d[1])
        : "r"(a[0]), "r"(a[1]), "r"(a[2]), "r"(a[3]), "r"(b[0]), "r"(b[1]));
}

// ---------------------------------------------------------------------------
// Split-precision conversion: fp32 -> (hi, lo) fp16, same layout
__global__ void convert_split(const float* __restrict__ in, __half* __restrict__ ohi,
                              __half* __restrict__ olo, size_t n4)
{
    size_t i = (size_t)blockIdx.x * blockDim.x + threadIdx.x;
    size_t stride = (size_t)gridDim.x * blockDim.x;
    for (; i < n4; i += stride) {
        float4 v = reinterpret_cast<const float4*>(in)[i];
        __half h0 = __float2half_rn(v.x), h1 = __float2half_rn(v.y);
        __half h2 = __float2half_rn(v.z), h3 = __float2half_rn(v.w);
        __half l0 = __float2half_rn(v.x - __half2float(h0));
        __half l1 = __float2half_rn(v.y - __half2float(h1));
        __half l2 = __float2half_rn(v.z - __half2float(h2));
        __half l3 = __float2half_rn(v.w - __half2float(h3));
        reinterpret_cast<__half2*>(ohi)[i * 2]     = __halves2half2(h0, h1);
        reinterpret_cast<__half2*>(ohi)[i * 2 + 1] = __halves2half2(h2, h3);
        reinterpret_cast<__half2*>(olo)[i * 2]     = __halves2half2(l0, l1);
        reinterpret_cast<__half2*>(olo)[i * 2 + 1] = __halves2half2(l2, l3);
    }
}

// Transposing split: in [K, N] fp32 row-major -> out hi/lo [N, K] fp16
__global__ void transpose_split(const float* __restrict__ in, int K, int N,
                                __half* __restrict__ ohi, __half* __restrict__ olo)
{
    __shared__ float t[32][33];
    int nb = blockIdx.x * 32, kb = blockIdx.y * 32;
    int tx = threadIdx.x, ty = threadIdx.y;  // (32, 8)
#pragma unroll
    for (int i = 0; i < 4; i++) {
        int kr = kb + ty + i * 8;
        t[ty + i * 8][tx] = in[(size_t)kr * N + nb + tx];
    }
    __syncthreads();
#pragma unroll
    for (int i = 0; i < 4; i++) {
        int nr = nb + ty + i * 8;
        float v = t[tx][ty + i * 8];
        __half h = __float2half_rn(v);
        __half l = __float2half_rn(v - __half2float(h));
        ohi[(size_t)nr * K + kb + tx] = h;
        olo[(size_t)nr * K + kb + tx] = l;
    }
}

// ---------------------------------------------------------------------------
// Split-fp16 HMMA GEMM:  C[128, 64] per CTA = relu(A·B^T + bias)
// hh -> fp32 accum; hl + lh corrections -> fp16 accum.
// 256 threads = 8 warps (4 x 2), warp tile 32x32, 3-stage cp.async pipeline.
// Slim tile + low regs => 2 CTAs/SM: independent CTAs overlap each other's
// CP_WAIT/barrier bubbles (whole-CTA stalls can't be hidden within one CTA).
// mode 0: write hi/lo fp16 (h1).  mode 1: write fp32 (h2).
// ---------------------------------------------------------------------------
#define BM 128
#define BN_ 64
#define BKH 32          // K halves per stage
#define PITCH 40        // halves per smem row (80 B, conflict-friendly)
#define A_BYTES (BM * PITCH * 2)        // 10240 per A array
#define B_BYTES (BN_ * PITCH * 2)       // 5120 per B array
#define SB_STAGE (2 * A_BYTES + 2 * B_BYTES)   // 30720: Ahi, Alo, Bhi, Blo
#define NSTAGE 3
#define GEMM_SMEM (NSTAGE * SB_STAGE)   // 92160 -> 2 CTAs/SM (184KB < 227KB)

__global__ __launch_bounds__(256, 2) void gemm_hmma_x3(
    const __half* __restrict__ Ahi, const __half* __restrict__ Alo,
    const __half* __restrict__ Bhi, const __half* __restrict__ Blo,
    const float* __restrict__ bias, int K, int ldc, int mode,
    __half* __restrict__ Ohi, __half* __restrict__ Olo, float* __restrict__ Of)
{
    extern __shared__ char smem[];
    const uint32_t sb = smem_u32(smem);
    const int tid = threadIdx.x, wid = tid >> 5, lane = tid & 31;
    const int m0 = blockIdx.y * BM, n0 = blockIdx.x * BN_;
    const int wm = wid & 3, wn = wid >> 2;     // warp grid 4 x 2, tile 32x32
    const int NC = K / BKH;

    float acc[2][4][4];                // hh pass, fp32
    uint32_t cacc[2][4][2];            // hl+lh corrections, f16x2
#pragma unroll
    for (int i = 0; i < 2; i++)
#pragma unroll
        for (int j = 0; j < 4; j++) {
#pragma unroll
            for (int k = 0; k < 4; k++) acc[i][j][k] = 0.0f;
            cacc[i][j][0] = 0u; cacc[i][j][1] = 0u;
        }

    // stage loader: 6 cp.async per thread (A 2x64-row passes, B 1x64-row pass)
    auto load_stage = [&](int s, int kc) {
        uint32_t st = sb + s * SB_STAGE;
        const int row = tid >> 2, seg = tid & 3;       // 64 rows x 4 x 16B
        const int kseg = kc + seg * 8;
#pragma unroll
        for (int h = 0; h < 2; h++) {
            int r = row + h * 64;
            uint32_t o = r * (PITCH * 2) + seg * 16;
            size_t ga = (size_t)(m0 + r) * K + kseg;
            cp16(st + o,           Ahi + ga);
            cp16(st + A_BYTES + o, Alo + ga);
        }
        {
            uint32_t o = row * (PITCH * 2) + seg * 16;
            size_t gb = (size_t)(n0 + row) * K + kseg;
            cp16(st + 2 * A_BYTES + o,           Bhi + gb);
            cp16(st + 2 * A_BYTES + B_BYTES + o, Blo + gb);
        }
        CP_COMMIT();
    };

    // per-lane ldmatrix addresses
    const int grp = lane >> 3, lr = lane & 7;
    const int a_row = (grp & 1) * 8 + lr;          // + m-tile base
    const int a_k   = (grp >> 1) * 8;
    const int b_row = (grp >> 1) * 8 + lr;         // + n-pair base
    const int b_k   = (grp & 1) * 8;

    // fragment buffers (single-buffered)
    uint32_t ah[2][4], al[2][4], bh[2][4], bl[2][4];

    auto load_frags = [&](int k16, uint32_t st) {
        const int koff = k16 * 16;
#pragma unroll
        for (int mt = 0; mt < 2; mt++) {
            uint32_t ao = (uint32_t)((wm * 32 + mt * 16 + a_row) * (PITCH * 2)
                                     + (koff + a_k) * 2);
            ldsm4(ah[mt], st + ao);
            ldsm4(al[mt], st + A_BYTES + ao);
        }
#pragma unroll
        for (int np = 0; np < 2; np++) {
            uint32_t bo = (uint32_t)((wn * 32 + np * 16 + b_row) * (PITCH * 2)
                                     + (koff + b_k) * 2);
            ldsm4(bh[np], st + 2 * A_BYTES + bo);
            ldsm4(bl[np], st + 2 * A_BYTES + B_BYTES + bo);
        }
    };

    // prologue: 2 stages in flight
    load_stage(0, 0);
    load_stage(1, BKH);

    for (int c = 0; c < NC; c++) {
        if (c == NC - 1) { CP_WAIT(0); } else { CP_WAIT(1); }
        __syncthreads();
        if (c + 2 < NC) load_stage((c + 2) % NSTAGE, (c + 2) * BKH);

        const uint32_t st = sb + (c % NSTAGE) * SB_STAGE;
#pragma unroll
        for (int k16 = 0; k16 < 2; k16++) {
            load_frags(k16, st);
            // pass hh (fp32 accum)
#pragma unroll
            for (int mt = 0; mt < 2; mt++)
#pragma unroll
                for (int nt = 0; nt < 4; nt++)
                    mma16816(acc[mt][nt], ah[mt], &bh[nt >> 1][(nt & 1) * 2]);
            // pass hl (fp16 accum)
#pragma unroll
            for (int mt = 0; mt < 2; mt++)
#pragma unroll
                for (int nt = 0; nt < 4; nt++)
                    mma16816h(cacc[mt][nt], ah[mt], &bl[nt >> 1][(nt & 1) * 2]);
            // pass lh (fp16 accum)
#pragma unroll
            for (int mt = 0; mt < 2; mt++)
#pragma unroll
                for (int nt = 0; nt < 4; nt++)
                    mma16816h(cacc[mt][nt], al[mt], &bh[nt >> 1][(nt & 1) * 2]);
        }
    }

    // epilogue: hh + correction + bias, relu, store
    const int cr = lane >> 2, ccol = (lane & 3) * 2;
#pragma unroll
    for (int mt = 0; mt < 2; mt++) {
#pragma unroll
        for (int nt = 0; nt < 4; nt++) {
            float* a4 = acc[mt][nt];
            __half2 c01 = *reinterpret_cast<__half2*>(&cacc[mt][nt][0]);
            __half2 c23 = *reinterpret_cast<__half2*>(&cacc[mt][nt][1]);
            int r0 = m0 + wm * 32 + mt * 16 + cr;
            int col = n0 + wn * 32 + nt * 8 + ccol;
            float bz0 = bias[col], bz1 = bias[col + 1];
            float v00 = fmaxf(a4[0] + __low2float(c01)  + bz0, 0.0f);
            float v01 = fmaxf(a4[1] + __high2float(c01) + bz1, 0.0f);
            float v10 = fmaxf(a4[2] + __low2float(c23)  + bz0, 0.0f);
            float v11 = fmaxf(a4[3] + __high2float(c23) + bz1, 0.0f);
            if (mode == 0) {
                __half h00 = __float2half_rn(v00), h01 = __float2half_rn(v01);
                __half h10 = __float2half_rn(v10), h11 = __float2half_rn(v11);
                __half l00 = __float2half_rn(v00 - __half2float(h00));
                __half l01 = __float2half_rn(v01 - __half2float(h01));
                __half l10 = __float2half_rn(v10 - __half2float(h10));
                __half l11 = __float2half_rn(v11 - __half2float(h11));
                *reinterpret_cast<__half2*>(Ohi + (size_t)r0 * ldc + col) = __halves2half2(h00, h01);
                *reinterpret_cast<__half2*>(Ohi + (size_t)(r0 + 8) * ldc + col) = __halves2half2(h10, h11);
                *reinterpret_cast<__half2*>(Olo + (size_t)r0 * ldc + col) = __halves2half2(l00, l01);
                *reinterpret_cast<__half2*>(Olo + (size_t)(r0 + 8) * ldc + col) = __halves2half2(l10, l11);
            } else {
                float2 f0 = {v00, v01}, f1 = {v10, v11};
                *reinterpret_cast<float2*>(Of + (size_t)r0 * ldc + col) = f0;
                *reinterpret_cast<float2*>(Of + (size_t)(r0 + 8) * ldc + col) = f1;
            }
        }
    }
}

// ---------------------------------------------------------------------------
// GEMM3 fused with per-chunk mean (reads g_h2)
__global__ void chunk_logits_kernel(const float* __restrict__ w3,
                                    const float* __restrict__ b3)
{
    __shared__ float w3s[H2 * EE];
    __shared__ float red[4][EE];
    const int tid = threadIdx.x;  // 128

    for (int i = tid; i < H2 * EE; i += 128) w3s[i] = w3[i];
    __syncthreads();

    const size_t tok = (size_t)blockIdx.x * 128 + tid;
    const float* hrow = g_h2 + tok * H2;
    float acc[EE];
#pragma unroll
    for (int e = 0; e < EE; e++) acc[e] = 0.0f;
    for (int k = 0; k < H2; k += 4) {
        float4 hv = *reinterpret_cast<const float4*>(hrow + k);
#pragma unroll
        for (int e = 0; e < EE; e++) {
            acc[e] = fmaf(hv.x, w3s[(k + 0) * EE + e], acc[e]);
            acc[e] = fmaf(hv.y, w3s[(k + 1) * EE + e], acc[e]);
            acc[e] = fmaf(hv.z, w3s[(k + 2) * EE + e], acc[e]);
            acc[e] = fmaf(hv.w, w3s[(k + 3) * EE + e], acc[e]);
        }
    }
    const int lane = tid & 31, warp = tid >> 5;
#pragma unroll
    for (int e = 0; e < EE; e++) {
        float v = acc[e];
#pragma unroll
        for (int o = 16; o > 0; o >>= 1) v += __shfl_down_sync(0xffffffffu, v, o);
        if (lane == 0) red[warp][e] = v;
    }
    __syncthreads();
    if (tid < EE) {
        float s = red[0][tid] + red[1][tid] + red[2][tid] + red[3][tid];
        g_cl[blockIdx.x * EE + tid] = s * (1.0f / 128.0f) + b3[tid];
    }
}

// ---------------------------------------------------------------------------
// finalize (1 block): hysteresis + stats + small outputs; saves sidx
__global__ void finalize_kernel(float* __restrict__ out)
{
    __shared__ float scl[BB * CC * EE];
    __shared__ int   sidx[BB * CC];
    __shared__ int   sflips[BB];
    __shared__ float sent[BB * CC];
    __shared__ float sutil[EE];
    __shared__ float sscal[3];
    const int tid = threadIdx.x;  // 128

    for (int i = tid; i < BB * CC * EE; i += 128) scl[i] = g_cl[i];
    if (tid < EE) sutil[tid] = 0.0f;
    __syncthreads();

    if (tid < BB) {
        int b = tid, prev = 0, flips = 0;
        for (int c = 0; c < CC; c++) {
            const float* l = &scl[(b * CC + c) * EE];
            int top = 0; float best = l[0];
#pragma unroll
            for (int e = 1; e < EE; e++)
                if (l[e] > best) { best = l[e]; top = e; }
            int fin;
            if (c == 0) fin = top;
            else {
                bool sw = (l[top] - l[prev]) > TAU_F;
                flips += sw ? 1 : 0;
                fin = sw ? top : prev;
            }
            sidx[b * CC + c] = fin;
            prev = fin;
        }
        sflips[tid] = flips;
    }
    __syncthreads();

    {
        const float* l = &scl[tid * EE];
        float mx = l[0];
#pragma unroll
        for (int e = 1; e < EE; e++) mx = fmaxf(mx, l[e]);
        float p[EE], se = 0.0f;
#pragma unroll
        for (int e = 0; e < EE; e++) { p[e] = expf(l[e] - mx); se += p[e]; }
        float ent = 0.0f, inv = 1.0f / se;
#pragma unroll
        for (int e = 0; e < EE; e++) {
            float pr = p[e] * inv;
            ent -= pr * logf(pr + 1e-8f);
        }
        sent[tid] = ent;
        atomicAdd(&sutil[sidx[tid]], 1.0f);
    }
    __syncthreads();

    if (tid == 0) {
        float es = 0.0f;
        for (int i = 0; i < BB * CC; i++) es += sent[i];
        sscal[0] = es / (float)(BB * CC);
        int fl = sflips[0] + sflips[1] + sflips[2] + sflips[3];
        sscal[1] = (float)fl / (float)(BB * (CC - 1));
        float nrm = 0.0f;
        for (int e = 0; e < EE; e++) {
            float u = sutil[e] / (float)(BB * CC);
            nrm += u * u;
        }
        sscal[2] = sqrtf(nrm);
    }
    __syncthreads();

    if (tid < BB * CC) { g_sidx[tid] = sidx[tid]; out[131072 + tid] = (float)sidx[tid]; }
    for (int i = tid; i < BB * CC * EE; i += 128) out[131200 + i] = scl[i];
    if (tid == 0) out[132224] = sscal[0];
    if (tid < EE) out[132225 + tid] = sutil[tid] / (float)(BB * CC);
    if (tid == 0) { out[132233] = sscal[1]; out[132234] = sscal[2]; }
}

// Wide routing_weights writer: one token (8 floats) per thread
__global__ void routing_weights_kernel(float* __restrict__ out)
{
    int t = blockIdx.x * blockDim.x + threadIdx.x;   // 0..16383
    int b = t >> 12;
    int c = (t >> 7) & 31;
    int id = g_sidx[b * CC + c];
    float vv[EE];
#pragma unroll
    for (int e = 0; e < EE; e++) vv[e] = (e == id) ? 1.0f : 0.0f;
    float4 v0 = {vv[0], vv[1], vv[2], vv[3]};
    float4 v1 = {vv[4], vv[5], vv[6], vv[7]};
    *reinterpret_cast<float4*>(out + (size_t)t * EE)     = v0;
    *reinterpret_cast<float4*>(out + (size_t)t * EE + 4) = v1;
}

// ---------------------------------------------------------------------------
extern "C" void kernel_launch(void* const* d_in, const int* in_sizes, int n_in,
                              void* d_out, int out_size)
{
    const float* x  = (const float*)d_in[0];
    // d_in[1] = prev_expert_indices — dead in reference (chunk 0 takes argmax)
    const float* w1 = (const float*)d_in[2];
    const float* b1 = (const float*)d_in[3];
    const float* w2 = (const float*)d_in[4];
    const float* b2 = (const float*)d_in[5];
    const float* w3 = (const float*)d_in[6];
    const float* b3 = (const float*)d_in[7];
    float* out = (float*)d_out;

    cudaFuncSetAttribute(gemm_hmma_x3, cudaFuncAttributeMaxDynamicSharedMemorySize, GEMM_SMEM);

    __half *xhi, *xlo, *w1hi, *w1lo, *h1hi, *h1lo, *w2hi, *w2lo;
    float *h2;
    cudaGetSymbolAddress((void**)&xhi, g_xhi);
    cudaGetSymbolAddress((void**)&xlo, g_xlo);
    cudaGetSymbolAddress((void**)&w1hi, g_w1hi);
    cudaGetSymbolAddress((void**)&w1lo, g_w1lo);
    cudaGetSymbolAddress((void**)&h1hi, g_h1hi);
    cudaGetSymbolAddress((void**)&h1lo, g_h1lo);
    cudaGetSymbolAddress((void**)&w2hi, g_w2hi);
    cudaGetSymbolAddress((void**)&w2lo, g_w2lo);
    cudaGetSymbolAddress((void**)&h2, g_h2);

    // input conversions
    convert_split<<<2048, 256>>>(x, xhi, xlo, (size_t)MM * DD / 4);
    transpose_split<<<dim3(HH / 32, DD / 32), dim3(32, 8)>>>(w1, DD, HH, w1hi, w1lo);
    transpose_split<<<dim3(H2 / 32, HH / 32), dim3(32, 8)>>>(w2, HH, H2, w2hi, w2lo);

    // GEMM1: [16384,2048] x [2048->1024] -> h1 (hi/lo fp16)
    gemm_hmma_x3<<<dim3(HH / BN_, MM / BM), 256, GEMM_SMEM>>>(
        xhi, xlo, w1hi, w1lo, b1, DD, HH, 0, h1hi, h1lo, nullptr);
    // GEMM2: [16384,1024] x [1024->512] -> h2 (fp32)
    gemm_hmma_x3<<<dim3(H2 / BN_, MM / BM), 256, GEMM_SMEM>>>(
        h1hi, h1lo, w2hi, w2lo, b2, HH, H2, 1, nullptr, nullptr, h2);

    chunk_logits_kernel<<<BB * CC, 128>>>(w3, b3);
    finalize_kernel<<<1, 128>>>(out);
    routing_weights_kernel<<<MM / 256, 256>>>(out);
}

// round 10
// speedup vs baseline: 1.5571x; 1.4612x over previous
#include <cuda_runtime.h>
#include <cuda_fp16.h>
#include <math.h>
#include <stdint.h>

// ---------------------------------------------------------------------------
// Problem constants
#define BB 4
#define SS_ 4096
#define DD 2048
#define HH 1024
#define H2 512
#define EE 8
#define CC 32
#define MM (BB * SS_)   // 16384
#define TAU_F 0.7f

// ---------------------------------------------------------------------------
// Scratch (device globals; no allocations allowed)
__device__ __half g_xhi[(size_t)MM * DD];
__device__ __half g_w1hi[(size_t)HH * DD];   // transposed [N=1024, K=2048]
__device__ __half g_w1lo[(size_t)HH * DD];
__device__ __half g_h1hi[(size_t)MM * HH];
__device__ __half g_w2hi[(size_t)H2 * HH];   // transposed [N=512, K=1024]
__device__ __half g_w2lo[(size_t)H2 * HH];
__device__ float  g_h2[(size_t)MM * H2];
__device__ float  g_cl[BB * CC * EE];
__device__ int    g_sidx[BB * CC];

// ---------------------------------------------------------------------------
__device__ __forceinline__ uint32_t smem_u32(const void* p) {
    uint32_t a;
    asm("{ .reg .u64 t; cvta.to.shared.u64 t, %1; cvt.u32.u64 %0, t; }"
        : "=r"(a) : "l"(p));
    return a;
}
__device__ __forceinline__ void cp16(uint32_t saddr, const void* gaddr) {
    asm volatile("cp.async.cg.shared.global [%0], [%1], 16;" :: "r"(saddr), "l"(gaddr));
}
#define CP_COMMIT() asm volatile("cp.async.commit_group;" ::: "memory")
#define CP_WAIT(n)  asm volatile("cp.async.wait_group %0;" :: "n"(n) : "memory")

__device__ __forceinline__ void ldsm4(uint32_t* r, uint32_t addr) {
    asm volatile("ldmatrix.sync.aligned.m8n8.x4.shared.b16 {%0,%1,%2,%3}, [%4];"
        : "=r"(r[0]), "=r"(r[1]), "=r"(r[2]), "=r"(r[3]) : "r"(addr));
}
// fp32-accumulator HMMA (main hi*hi pass)
__device__ __forceinline__ void mma16816(float* d, const uint32_t* a, const uint32_t* b) {
    asm volatile("mma.sync.aligned.m16n8k16.row.col.f32.f16.f16.f32 "
        "{%0,%1,%2,%3}, {%4,%5,%6,%7}, {%8,%9}, {%0,%1,%2,%3};"
        : "+f"(d[0]), "+f"(d[1]), "+f"(d[2]), "+f"(d[3])
        : "r"(a[0]), "r"(a[1]), "r"(a[2]), "r"(a[3]), "r"(b[0]), "r"(b[1]));
}
// fp16-accumulator HMMA (weight-residual correction pass; terms ~2^-11 of main)
__device__ __forceinline__ void mma16816h(uint32_t* d, const uint32_t* a, const uint32_t* b) {
    asm volatile("mma.sync.aligned.m16n8k16.row.col.f16.f16.f16.f16 "
        "{%0,%1}, {%2,%3,%4,%5}, {%6,%7}, {%0,%1};"
        : "+r"(d[0]), "+r"(d[1])
        : "r"(a[0]), "r"(a[1]), "r"(a[2]), "r"(a[3]), "r"(b[0]), "r"(b[1]));
}

// ---------------------------------------------------------------------------
// fp32 -> fp16 (hi only) conversion for activations: token-residual error is
// iid across the 128 tokens of a chunk and is suppressed by the chunk-mean.
__global__ void convert_hi(const float* __restrict__ in, __half* __restrict__ ohi,
                           size_t n4)
{
    size_t i = (size_t)blockIdx.x * blockDim.x + threadIdx.x;
    size_t stride = (size_t)gridDim.x * blockDim.x;
    for (; i < n4; i += stride) {
        float4 v = reinterpret_cast<const float4*>(in)[i];
        reinterpret_cast<__half2*>(ohi)[i * 2] =
            __halves2half2(__float2half_rn(v.x), __float2half_rn(v.y));
        reinterpret_cast<__half2*>(ohi)[i * 2 + 1] =
            __halves2half2(__float2half_rn(v.z), __float2half_rn(v.w));
    }
}

// Transposing split: in [K, N] fp32 row-major -> out hi/lo [N, K] fp16.
// Weight residuals are systematic (shared by all tokens) so they keep a
// correction pass.
__global__ void transpose_split(const float* __restrict__ in, int K, int N,
                                __half* __restrict__ ohi, __half* __restrict__ olo)
{
    __shared__ float t[32][33];
    int nb = blockIdx.x * 32, kb = blockIdx.y * 32;
    int tx = threadIdx.x, ty = threadIdx.y;  // (32, 8)
#pragma unroll
    for (int i = 0; i < 4; i++) {
        int kr = kb + ty + i * 8;
        t[ty + i * 8][tx] = in[(size_t)kr * N + nb + tx];
    }
    __syncthreads();
#pragma unroll
    for (int i = 0; i < 4; i++) {
        int nr = nb + ty + i * 8;
        float v = t[tx][ty + i * 8];
        __half h = __float2half_rn(v);
        __half l = __float2half_rn(v - __half2float(h));
        ohi[(size_t)nr * K + kb + tx] = h;
        olo[(size_t)nr * K + kb + tx] = l;
    }
}

// ---------------------------------------------------------------------------
// 2-pass split-fp16 HMMA GEMM:  C[128, 64] per CTA = relu(A·B^T + bias)
// hh (fp32 acc) + hl = Ahi·Blo (fp16 acc, weight-residual correction).
// The dropped Alo·Bhi term is token-iid and averaged out by the chunk-mean.
// 256 threads = 8 warps (4 x 2), warp tile 32x32, 3-stage cp.async pipeline,
// 2 CTAs/SM. We sit on the legacy-HMMA instruction-rate floor, so wall time
// scales with MMA instruction count: 2 passes instead of 3.
// mode 0: write fp16 hi (h1).  mode 1: write fp32 (h2).
// ---------------------------------------------------------------------------
#define BM 128
#define BN_ 64
#define BKH 32          // K halves per stage
#define PITCH 40        // halves per smem row (80 B, conflict-friendly)
#define A_BYTES (BM * PITCH * 2)        // 10240
#define B_BYTES (BN_ * PITCH * 2)       // 5120 per B array
#define SB_STAGE (A_BYTES + 2 * B_BYTES)   // 20480: Ahi, Bhi, Blo
#define NSTAGE 3
#define GEMM_SMEM (NSTAGE * SB_STAGE)   // 61440 -> 2 CTAs/SM

__global__ __launch_bounds__(256, 2) void gemm_hmma_x2(
    const __half* __restrict__ Ahi,
    const __half* __restrict__ Bhi, const __half* __restrict__ Blo,
    const float* __restrict__ bias, int K, int ldc, int mode,
    __half* __restrict__ Ohi, float* __restrict__ Of)
{
    extern __shared__ char smem[];
    const uint32_t sb = smem_u32(smem);
    const int tid = threadIdx.x, wid = tid >> 5, lane = tid & 31;
    const int m0 = blockIdx.y * BM, n0 = blockIdx.x * BN_;
    const int wm = wid & 3, wn = wid >> 2;     // warp grid 4 x 2, tile 32x32
    const int NC = K / BKH;

    float acc[2][4][4];                // hh pass, fp32
    uint32_t cacc[2][4][2];            // hl correction, f16x2
#pragma unroll
    for (int i = 0; i < 2; i++)
#pragma unroll
        for (int j = 0; j < 4; j++) {
#pragma unroll
            for (int k = 0; k < 4; k++) acc[i][j][k] = 0.0f;
            cacc[i][j][0] = 0u; cacc[i][j][1] = 0u;
        }

    // stage loader: A 512 segs (2/thread), B arrays 256 segs (1/thread each)
    auto load_stage = [&](int s, int kc) {
        uint32_t st = sb + s * SB_STAGE;
#pragma unroll
        for (int i = 0; i < 2; i++) {
            int s4 = tid + i * 256;
            int row = s4 >> 2, seg = s4 & 3;
            cp16(st + row * (PITCH * 2) + seg * 16,
                 Ahi + (size_t)(m0 + row) * K + kc + seg * 8);
        }
        {
            int row = tid >> 2, seg = tid & 3;
            uint32_t o = row * (PITCH * 2) + seg * 16;
            size_t gb = (size_t)(n0 + row) * K + kc + seg * 8;
            cp16(st + A_BYTES + o,           Bhi + gb);
            cp16(st + A_BYTES + B_BYTES + o, Blo + gb);
        }
        CP_COMMIT();
    };

    // per-lane ldmatrix addresses
    const int grp = lane >> 3, lr = lane & 7;
    const int a_row = (grp & 1) * 8 + lr;          // + m-tile base
    const int a_k   = (grp >> 1) * 8;
    const int b_row = (grp >> 1) * 8 + lr;         // + n-pair base
    const int b_k   = (grp & 1) * 8;

    uint32_t ah[2][4], bh[2][4], bl[2][4];

    auto load_frags = [&](int k16, uint32_t st) {
        const int koff = k16 * 16;
#pragma unroll
        for (int mt = 0; mt < 2; mt++) {
            uint32_t ao = (uint32_t)((wm * 32 + mt * 16 + a_row) * (PITCH * 2)
                                     + (koff + a_k) * 2);
            ldsm4(ah[mt], st + ao);
        }
#pragma unroll
        for (int np = 0; np < 2; np++) {
            uint32_t bo = (uint32_t)((wn * 32 + np * 16 + b_row) * (PITCH * 2)
                                     + (koff + b_k) * 2);
            ldsm4(bh[np], st + A_BYTES + bo);
            ldsm4(bl[np], st + A_BYTES + B_BYTES + bo);
        }
    };

    // prologue: 2 stages in flight
    load_stage(0, 0);
    load_stage(1, BKH);

    for (int c = 0; c < NC; c++) {
        if (c == NC - 1) { CP_WAIT(0); } else { CP_WAIT(1); }
        __syncthreads();
        if (c + 2 < NC) load_stage((c + 2) % NSTAGE, (c + 2) * BKH);

        const uint32_t st = sb + (c % NSTAGE) * SB_STAGE;
#pragma unroll
        for (int k16 = 0; k16 < 2; k16++) {
            load_frags(k16, st);
            // pass hh (fp32 accum)
#pragma unroll
            for (int mt = 0; mt < 2; mt++)
#pragma unroll
                for (int nt = 0; nt < 4; nt++)
                    mma16816(acc[mt][nt], ah[mt], &bh[nt >> 1][(nt & 1) * 2]);
            // pass hl (fp16 accum): Ahi * Blo
#pragma unroll
            for (int mt = 0; mt < 2; mt++)
#pragma unroll
                for (int nt = 0; nt < 4; nt++)
                    mma16816h(cacc[mt][nt], ah[mt], &bl[nt >> 1][(nt & 1) * 2]);
        }
    }

    // epilogue: hh + correction + bias, relu, store
    const int cr = lane >> 2, ccol = (lane & 3) * 2;
#pragma unroll
    for (int mt = 0; mt < 2; mt++) {
#pragma unroll
        for (int nt = 0; nt < 4; nt++) {
            float* a4 = acc[mt][nt];
            __half2 c01 = *reinterpret_cast<__half2*>(&cacc[mt][nt][0]);
            __half2 c23 = *reinterpret_cast<__half2*>(&cacc[mt][nt][1]);
            int r0 = m0 + wm * 32 + mt * 16 + cr;
            int col = n0 + wn * 32 + nt * 8 + ccol;
            float bz0 = bias[col], bz1 = bias[col + 1];
            float v00 = fmaxf(a4[0] + __low2float(c01)  + bz0, 0.0f);
            float v01 = fmaxf(a4[1] + __high2float(c01) + bz1, 0.0f);
            float v10 = fmaxf(a4[2] + __low2float(c23)  + bz0, 0.0f);
            float v11 = fmaxf(a4[3] + __high2float(c23) + bz1, 0.0f);
            if (mode == 0) {
                *reinterpret_cast<__half2*>(Ohi + (size_t)r0 * ldc + col) =
                    __halves2half2(__float2half_rn(v00), __float2half_rn(v01));
                *reinterpret_cast<__half2*>(Ohi + (size_t)(r0 + 8) * ldc + col) =
                    __halves2half2(__float2half_rn(v10), __float2half_rn(v11));
            } else {
                float2 f0 = {v00, v01}, f1 = {v10, v11};
                *reinterpret_cast<float2*>(Of + (size_t)r0 * ldc + col) = f0;
                *reinterpret_cast<float2*>(Of + (size_t)(r0 + 8) * ldc + col) = f1;
            }
        }
    }
}

// ---------------------------------------------------------------------------
// GEMM3 fused with per-chunk mean (reads g_h2)
__global__ void chunk_logits_kernel(const float* __restrict__ w3,
                                    const float* __restrict__ b3)
{
    __shared__ float w3s[H2 * EE];
    __shared__ float red[4][EE];
    const int tid = threadIdx.x;  // 128

    for (int i = tid; i < H2 * EE; i += 128) w3s[i] = w3[i];
    __syncthreads();

    const size_t tok = (size_t)blockIdx.x * 128 + tid;
    const float* hrow = g_h2 + tok * H2;
    float acc[EE];
#pragma unroll
    for (int e = 0; e < EE; e++) acc[e] = 0.0f;
    for (int k = 0; k < H2; k += 4) {
        float4 hv = *reinterpret_cast<const float4*>(hrow + k);
#pragma unroll
        for (int e = 0; e < EE; e++) {
            acc[e] = fmaf(hv.x, w3s[(k + 0) * EE + e], acc[e]);
            acc[e] = fmaf(hv.y, w3s[(k + 1) * EE + e], acc[e]);
            acc[e] = fmaf(hv.z, w3s[(k + 2) * EE + e], acc[e]);
            acc[e] = fmaf(hv.w, w3s[(k + 3) * EE + e], acc[e]);
        }
    }
    const int lane = tid & 31, warp = tid >> 5;
#pragma unroll
    for (int e = 0; e < EE; e++) {
        float v = acc[e];
#pragma unroll
        for (int o = 16; o > 0; o >>= 1) v += __shfl_down_sync(0xffffffffu, v, o);
        if (lane == 0) red[warp][e] = v;
    }
    __syncthreads();
    if (tid < EE) {
        float s = red[0][tid] + red[1][tid] + red[2][tid] + red[3][tid];
        g_cl[blockIdx.x * EE + tid] = s * (1.0f / 128.0f) + b3[tid];
    }
}

// ---------------------------------------------------------------------------
// finalize (1 block): hysteresis + stats + small outputs; saves sidx
__global__ void finalize_kernel(float* __restrict__ out)
{
    __shared__ float scl[BB * CC * EE];
    __shared__ int   sidx[BB * CC];
    __shared__ int   sflips[BB];
    __shared__ float sent[BB * CC];
    __shared__ float sutil[EE];
    __shared__ float sscal[3];
    const int tid = threadIdx.x;  // 128

    for (int i = tid; i < BB * CC * EE; i += 128) scl[i] = g_cl[i];
    if (tid < EE) sutil[tid] = 0.0f;
    __syncthreads();

    if (tid < BB) {
        int b = tid, prev = 0, flips = 0;
        for (int c = 0; c < CC; c++) {
            const float* l = &scl[(b * CC + c) * EE];
            int top = 0; float best = l[0];
#pragma unroll
            for (int e = 1; e < EE; e++)
                if (l[e] > best) { best = l[e]; top = e; }
            int fin;
            if (c == 0) fin = top;
            else {
                bool sw = (l[top] - l[prev]) > TAU_F;
                flips += sw ? 1 : 0;
                fin = sw ? top : prev;
            }
            sidx[b * CC + c] = fin;
            prev = fin;
        }
        sflips[tid] = flips;
    }
    __syncthreads();

    {
        const float* l = &scl[tid * EE];
        float mx = l[0];
#pragma unroll
        for (int e = 1; e < EE; e++) mx = fmaxf(mx, l[e]);
        float p[EE], se = 0.0f;
#pragma unroll
        for (int e = 0; e < EE; e++) { p[e] = expf(l[e] - mx); se += p[e]; }
        float ent = 0.0f, inv = 1.0f / se;
#pragma unroll
        for (int e = 0; e < EE; e++) {
            float pr = p[e] * inv;
            ent -= pr * logf(pr + 1e-8f);
        }
        sent[tid] = ent;
        atomicAdd(&sutil[sidx[tid]], 1.0f);
    }
    __syncthreads();

    if (tid == 0) {
        float es = 0.0f;
        for (int i = 0; i < BB * CC; i++) es += sent[i];
        sscal[0] = es / (float)(BB * CC);
        int fl = sflips[0] + sflips[1] + sflips[2] + sflips[3];
        sscal[1] = (float)fl / (float)(BB * (CC - 1));
        float nrm = 0.0f;
        for (int e = 0; e < EE; e++) {
            float u = sutil[e] / (float)(BB * CC);
            nrm += u * u;
        }
        sscal[2] = sqrtf(nrm);
    }
    __syncthreads();

    if (tid < BB * CC) { g_sidx[tid] = sidx[tid]; out[131072 + tid] = (float)sidx[tid]; }
    for (int i = tid; i < BB * CC * EE; i += 128) out[131200 + i] = scl[i];
    if (tid == 0) out[132224] = sscal[0];
    if (tid < EE) out[132225 + tid] = sutil[tid] / (float)(BB * CC);
    if (tid == 0) { out[132233] = sscal[1]; out[132234] = sscal[2]; }
}

// Wide routing_weights writer: one token (8 floats) per thread
__global__ void routing_weights_kernel(float* __restrict__ out)
{
    int t = blockIdx.x * blockDim.x + threadIdx.x;   // 0..16383
    int b = t >> 12;
    int c = (t >> 7) & 31;
    int id = g_sidx[b * CC + c];
    float vv[EE];
#pragma unroll
    for (int e = 0; e < EE; e++) vv[e] = (e == id) ? 1.0f : 0.0f;
    float4 v0 = {vv[0], vv[1], vv[2], vv[3]};
    float4 v1 = {vv[4], vv[5], vv[6], vv[7]};
    *reinterpret_cast<float4*>(out + (size_t)t * EE)     = v0;
    *reinterpret_cast<float4*>(out + (size_t)t * EE + 4) = v1;
}

// ---------------------------------------------------------------------------
extern "C" void kernel_launch(void* const* d_in, const int* in_sizes, int n_in,
                              void* d_out, int out_size)
{
    const float* x  = (const float*)d_in[0];
    // d_in[1] = prev_expert_indices — dead in reference (chunk 0 takes argmax)
    const float* w1 = (const float*)d_in[2];
    const float* b1 = (const float*)d_in[3];
    const float* w2 = (const float*)d_in[4];
    const float* b2 = (const float*)d_in[5];
    const float* w3 = (const float*)d_in[6];
    const float* b3 = (const float*)d_in[7];
    float* out = (float*)d_out;

    cudaFuncSetAttribute(gemm_hmma_x2, cudaFuncAttributeMaxDynamicSharedMemorySize, GEMM_SMEM);

    __half *xhi, *w1hi, *w1lo, *h1hi, *w2hi, *w2lo;
    float *h2;
    cudaGetSymbolAddress((void**)&xhi, g_xhi);
    cudaGetSymbolAddress((void**)&w1hi, g_w1hi);
    cudaGetSymbolAddress((void**)&w1lo, g_w1lo);
    cudaGetSymbolAddress((void**)&h1hi, g_h1hi);
    cudaGetSymbolAddress((void**)&w2hi, g_w2hi);
    cudaGetSymbolAddress((void**)&w2lo, g_w2lo);
    cudaGetSymbolAddress((void**)&h2, g_h2);

    // input conversions
    convert_hi<<<2048, 256>>>(x, xhi, (size_t)MM * DD / 4);
    transpose_split<<<dim3(HH / 32, DD / 32), dim3(32, 8)>>>(w1, DD, HH, w1hi, w1lo);
    transpose_split<<<dim3(H2 / 32, HH / 32), dim3(32, 8)>>>(w2, HH, H2, w2hi, w2lo);

    // GEMM1: [16384,2048] x [2048->1024] -> h1 (fp16)
    gemm_hmma_x2<<<dim3(HH / BN_, MM / BM), 256, GEMM_SMEM>>>(
        xhi, w1hi, w1lo, b1, DD, HH, 0, h1hi, nullptr);
    // GEMM2: [16384,1024] x [1024->512] -> h2 (fp32)
    gemm_hmma_x2<<<dim3(H2 / BN_, MM / BM), 256, GEMM_SMEM>>>(
        h1hi, w2hi, w2lo, b2, HH, H2, 1, nullptr, h2);

    chunk_logits_kernel<<<BB * CC, 128>>>(w3, b3);
    finalize_kernel<<<1, 128>>>(out);
    routing_weights_kernel<<<MM / 256, 256>>>(out);
}